// round 5
// baseline (speedup 1.0000x reference)
#include <cuda_runtime.h>
#include <cuda_bf16.h>

// Problem constants
#define BB   512
#define SS   1024
#define FIN  16      // features per (b,s); feature 15 is delta
#define HH   64
#define GG   192     // 3*H
#define NB   4       // batches per CTA
#define NT   384     // 12 warps: thread = (g in [0,192), pr in {0,1} batch-pair)
#define NCTA (BB/NB) // 128

typedef unsigned long long u64;

// ---- packed f32x2 helpers (bit-exact fp32, 2 FMA per fma-pipe slot) ----
__device__ __forceinline__ u64 pack2(float lo, float hi) {
    u64 r; asm("mov.b64 %0, {%1, %2};" : "=l"(r) : "f"(lo), "f"(hi)); return r;
}
__device__ __forceinline__ void unpack2(u64 v, float& lo, float& hi) {
    asm("mov.b64 {%0, %1}, %2;" : "=f"(lo), "=f"(hi) : "l"(v));
}
__device__ __forceinline__ u64 fma2(u64 a, u64 b, u64 c) {
    u64 d; asm("fma.rn.f32x2 %0, %1, %2, %3;" : "=l"(d) : "l"(a), "l"(b), "l"(c)); return d;
}
__device__ __forceinline__ u64 add2(u64 a, u64 b) {
    u64 d; asm("add.rn.f32x2 %0, %1, %2;" : "=l"(d) : "l"(a), "l"(b)); return d;
}

__device__ __forceinline__ float sigmoidf_(float x) {
    return __fdividef(1.0f, 1.0f + __expf(-x));
}
__device__ __forceinline__ float tanhf_(float x) {
    return __fdividef(2.0f, 1.0f + __expf(-2.0f * x)) - 1.0f;
}

__global__ __launch_bounds__(NT, 1)
void gru_scan_kernel(const float* __restrict__ inputs,   // (B,S,16)
                     const float* __restrict__ k_in,     // (15,192)
                     const float* __restrict__ r_in,     // (64,192)
                     const float* __restrict__ bias,     // (2,192)
                     const float* __restrict__ w1,       // (64,64)
                     const float* __restrict__ b1,       // (64)
                     const float* __restrict__ bn_gamma,
                     const float* __restrict__ bn_beta,
                     const float* __restrict__ bn_mean,
                     const float* __restrict__ bn_var,
                     const float* __restrict__ w2,       // (64,1)
                     const float* __restrict__ b2,       // (1)
                     const float* __restrict__ Tp,       // (1)
                     float* __restrict__ out)            // (B,1)
{
    __shared__ __align__(16) float sm_h[NB][HH];      // hidden state (single buffer)
    __shared__ __align__(16) float sm_x[2][NB][FIN];  // double-buffered step inputs
    __shared__ __align__(16) float sm_s[NB][256];     // pre-activations staging
    __shared__ float sm_d[NB];
    __shared__ float sm_e[NB][HH];

    const int tid   = threadIdx.x;
    const int g     = tid % GG;          // output column 0..191
    const int pr    = tid / GG;          // 0 -> batches 0,1 ; 1 -> batches 2,3
    const int b0    = pr * 2;
    const int bbase = blockIdx.x * NB;

    // ---- Per-column weights in registers, packed as f32x2 pairs over k ----
    u64 R2[32];
    #pragma unroll
    for (int k2 = 0; k2 < 32; k2++)
        R2[k2] = pack2(r_in[(2 * k2) * GG + g], r_in[(2 * k2 + 1) * GG + g]);
    u64 K2[8];
    #pragma unroll
    for (int f2 = 0; f2 < 8; f2++) {
        float lo = k_in[(2 * f2) * GG + g];
        float hi = (2 * f2 + 1 < 15) ? k_in[(2 * f2 + 1) * GG + g] : 0.0f; // lane 15 (delta) masked
        K2[f2] = pack2(lo, hi);
    }
    const float bi = bias[g];
    const float br = bias[GG + g];

    // init h = 0
    if (tid < NB * HH) ((float*)sm_h)[tid] = 0.0f;
    // preload x(0) -> sm_x[0], x(1) -> sm_x[1]
    if (tid < NB * 4 * 2) {
        int buf = tid >> 4, b = (tid >> 2) & 3, q = tid & 3;
        ((float4*)sm_x[buf][b])[q] =
            *(const float4*)&inputs[((size_t)(bbase + b) * SS + buf) * FIN + (size_t)q * 4];
    }
    __syncthreads();

    // ---- pre-loop: vx(0) from sm_x[0] ----
    float vx[2];
    {
        #pragma unroll
        for (int u = 0; u < 2; u++) {
            const ulonglong2* x4 = (const ulonglong2*)sm_x[0][b0 + u];
            u64 c0 = 0ull, c1 = 0ull;
            #pragma unroll
            for (int q = 0; q < 4; q += 2) {
                ulonglong2 xv0 = x4[q];
                ulonglong2 xv1 = x4[q + 1];
                c0 = fma2(xv0.x, K2[2 * q],     c0);
                c1 = fma2(xv0.y, K2[2 * q + 1], c1);
                c0 = fma2(xv1.x, K2[2 * q + 2], c0);
                c1 = fma2(xv1.y, K2[2 * q + 3], c1);
            }
            float lo, hi; unpack2(add2(c0, c1), lo, hi);
            vx[u] = bi + (lo + hi);
        }
    }
    float dsum = 0.0f;
    if (tid < NB) dsum = sm_x[0][tid][15];

    for (int s = 0; s < SS; s++) {
        // ---------- Phase A: recurrent dot only (vr = h.R + br) ----------
        float vr[2];
        #pragma unroll
        for (int u = 0; u < 2; u++) {
            const ulonglong2* h4 = (const ulonglong2*)sm_h[b0 + u];  // LDS.128 broadcast
            u64 a0 = 0ull, a1 = 0ull, a2 = 0ull, a3 = 0ull;
            #pragma unroll
            for (int q = 0; q < 16; q += 2) {
                ulonglong2 hv0 = h4[q];
                ulonglong2 hv1 = h4[q + 1];
                a0 = fma2(hv0.x, R2[2 * q],     a0);
                a1 = fma2(hv0.y, R2[2 * q + 1], a1);
                a2 = fma2(hv1.x, R2[2 * q + 2], a2);
                a3 = fma2(hv1.y, R2[2 * q + 3], a3);
            }
            float lo, hi; unpack2(add2(add2(a0, a1), add2(a2, a3)), lo, hi);
            vr[u] = br + (lo + hi);
        }

        #pragma unroll
        for (int u = 0; u < 2; u++) {
            const int b = b0 + u;
            if (g < 128) {
                sm_s[b][g] = vx[u] + vr[u];        // z-pre / r-pre combined
            } else {
                sm_s[b][g]      = vx[u];           // xh
                sm_s[b][g + 64] = vr[u];           // rh
            }
        }
        __syncthreads();

        // ---------- Phase B: prefetch x(s+2), compute vx(s+1), gates ----------
        if (s + 2 < SS && tid < NB * 4) {
            int b = tid >> 2, q = tid & 3;
            ((float4*)sm_x[s & 1][b])[q] =
                *(const float4*)&inputs[((size_t)(bbase + b) * SS + (s + 2)) * FIN +
                                        (size_t)q * 4];
        }
        if (s + 1 < SS) {
            const int nb = (s + 1) & 1;
            #pragma unroll
            for (int u = 0; u < 2; u++) {
                const ulonglong2* x4 = (const ulonglong2*)sm_x[nb][b0 + u];
                u64 c0 = 0ull, c1 = 0ull;
                #pragma unroll
                for (int q = 0; q < 4; q += 2) {
                    ulonglong2 xv0 = x4[q];
                    ulonglong2 xv1 = x4[q + 1];
                    c0 = fma2(xv0.x, K2[2 * q],     c0);
                    c1 = fma2(xv0.y, K2[2 * q + 1], c1);
                    c0 = fma2(xv1.x, K2[2 * q + 2], c0);
                    c1 = fma2(xv1.y, K2[2 * q + 3], c1);
                }
                float lo, hi; unpack2(add2(c0, c1), lo, hi);
                vx[u] = bi + (lo + hi);
            }
            if (tid < NB) dsum += sm_x[nb][tid][15];
        }
        if (tid < NB * HH) {
            int b = tid >> 6, j = tid & 63;
            float z  = sigmoidf_(sm_s[b][j]);
            float r  = sigmoidf_(sm_s[b][64 + j]);
            float hh = tanhf_(sm_s[b][128 + j] + r * sm_s[b][192 + j]);
            float ho = sm_h[b][j];
            sm_h[b][j] = z * (ho - hh) + hh;
        }
        __syncthreads();
    }

    // ---------- Epilogue: delta effect + MLP head + BN ----------
    if (tid < NB) sm_d[tid] = Tp[0] * dsum * (1.0f / (float)SS);
    __syncthreads();

    if (tid < NB * HH) {
        int b = tid >> 6, jj = tid & 63;
        float db  = sm_d[b];
        float acc = b1[jj];
        #pragma unroll 8
        for (int k = 0; k < HH; k++)
            acc += (sm_h[b][k] + db) * w1[k * HH + jj];
        float hr = fmaxf(acc, 0.0f);
        float hb = (hr - bn_mean[jj]) * rsqrtf(bn_var[jj] + 1e-3f) * bn_gamma[jj] + bn_beta[jj];
        sm_e[b][jj] = hb * w2[jj];
    }
    __syncthreads();

    if (tid < NB) {
        float acc = b2[0];
        #pragma unroll 8
        for (int jj = 0; jj < HH; jj++) acc += sm_e[tid][jj];
        out[bbase + tid] = acc;
    }
}

extern "C" void kernel_launch(void* const* d_in, const int* in_sizes, int n_in,
                              void* d_out, int out_size) {
    const float* inputs   = (const float*)d_in[0];
    const float* gk       = (const float*)d_in[1];
    const float* grk      = (const float*)d_in[2];
    const float* gbias    = (const float*)d_in[3];
    const float* w1       = (const float*)d_in[4];
    const float* b1       = (const float*)d_in[5];
    const float* bn_gamma = (const float*)d_in[6];
    const float* bn_beta  = (const float*)d_in[7];
    const float* bn_mean  = (const float*)d_in[8];
    const float* bn_var   = (const float*)d_in[9];
    const float* w2       = (const float*)d_in[10];
    const float* b2       = (const float*)d_in[11];
    const float* T        = (const float*)d_in[12];
    float* out = (float*)d_out;

    gru_scan_kernel<<<NCTA, NT>>>(inputs, gk, grk, gbias, w1, b1,
                                  bn_gamma, bn_beta, bn_mean, bn_var,
                                  w2, b2, T, out);
}

// round 6
// speedup vs baseline: 1.5180x; 1.5180x over previous
#include <cuda_runtime.h>
#include <cuda_bf16.h>

// Problem constants
#define BB   512
#define SS   1024
#define FIN  16      // features per (b,s); feature 15 is delta
#define HH   64
#define GG   192     // 3*H
#define NB   2       // batches per CTA
#define NT   192     // 6 warps; one thread per output column g, handling both batches
#define NCTA (BB/NB) // 256 -> 2 CTAs per SM resident (108 SMs x2, 40 SMs x1)

typedef unsigned long long u64;

// ---- packed f32x2 helpers (bit-exact fp32, 2 FMA per fma-pipe slot) ----
__device__ __forceinline__ u64 pack2(float lo, float hi) {
    u64 r; asm("mov.b64 %0, {%1, %2};" : "=l"(r) : "f"(lo), "f"(hi)); return r;
}
__device__ __forceinline__ void unpack2(u64 v, float& lo, float& hi) {
    asm("mov.b64 {%0, %1}, %2;" : "=f"(lo), "=f"(hi) : "l"(v));
}
__device__ __forceinline__ u64 fma2(u64 a, u64 b, u64 c) {
    u64 d; asm("fma.rn.f32x2 %0, %1, %2, %3;" : "=l"(d) : "l"(a), "l"(b), "l"(c)); return d;
}
__device__ __forceinline__ u64 add2(u64 a, u64 b) {
    u64 d; asm("add.rn.f32x2 %0, %1, %2;" : "=l"(d) : "l"(a), "l"(b)); return d;
}

__device__ __forceinline__ float sigmoidf_(float x) {
    return __fdividef(1.0f, 1.0f + __expf(-x));
}
__device__ __forceinline__ float tanhf_(float x) {
    return __fdividef(2.0f, 1.0f + __expf(-2.0f * x)) - 1.0f;
}

__global__ __launch_bounds__(NT, 2)
void gru_scan_kernel(const float* __restrict__ inputs,   // (B,S,16)
                     const float* __restrict__ k_in,     // (15,192)
                     const float* __restrict__ r_in,     // (64,192)
                     const float* __restrict__ bias,     // (2,192)
                     const float* __restrict__ w1,       // (64,64)
                     const float* __restrict__ b1,       // (64)
                     const float* __restrict__ bn_gamma,
                     const float* __restrict__ bn_beta,
                     const float* __restrict__ bn_mean,
                     const float* __restrict__ bn_var,
                     const float* __restrict__ w2,       // (64,1)
                     const float* __restrict__ b2,       // (1)
                     const float* __restrict__ Tp,       // (1)
                     float* __restrict__ out)            // (B,1)
{
    __shared__ __align__(16) float sm_h[NB][HH];    // hidden state per batch
    __shared__ __align__(16) float sm_x[NB][FIN];   // current-step inputs
    __shared__ __align__(16) float sm_s[NB][256];   // [0:128)=z/r-pre ; [128:192)=xh ; [192:256)=rh
    __shared__ float sm_d[NB];
    __shared__ float sm_e[NB][HH];

    const int tid   = threadIdx.x;
    const int g     = tid;               // output column 0..191
    const int bbase = blockIdx.x * NB;

    // ---- Per-column weights in registers, packed as f32x2 pairs over k ----
    u64 R2[32];
    #pragma unroll
    for (int k2 = 0; k2 < 32; k2++)
        R2[k2] = pack2(r_in[(2 * k2) * GG + g], r_in[(2 * k2 + 1) * GG + g]);
    u64 K2[8];
    #pragma unroll
    for (int f2 = 0; f2 < 8; f2++) {
        float lo = k_in[(2 * f2) * GG + g];
        float hi = (2 * f2 + 1 < 15) ? k_in[(2 * f2 + 1) * GG + g] : 0.0f; // lane 15 (delta) masked
        K2[f2] = pack2(lo, hi);
    }
    const float bi = bias[g];
    const float br = bias[GG + g];

    // init h = 0
    if (tid < NB * HH) ((float*)sm_h)[tid] = 0.0f;
    // preload x for s=0
    if (tid < NB * 4) {
        int b = tid >> 2, q = tid & 3;
        ((float4*)sm_x[b])[q] =
            *(const float4*)&inputs[(size_t)(bbase + b) * SS * FIN + (size_t)q * 4];
    }
    float dsum = 0.0f;
    __syncthreads();

    for (int s = 0; s < SS; s++) {
        // ---------- Phase A: per-column GEMV via f32x2 (both dots, max ILP) ----------
        float vx[NB], vr[NB];
        #pragma unroll
        for (int b = 0; b < NB; b++) {
            const ulonglong2* h4 = (const ulonglong2*)sm_h[b];  // LDS.128 broadcasts
            u64 a0 = 0ull, a1 = 0ull, a2 = 0ull, a3 = 0ull;
            #pragma unroll
            for (int q = 0; q < 16; q += 2) {
                ulonglong2 hv0 = h4[q];
                ulonglong2 hv1 = h4[q + 1];
                a0 = fma2(hv0.x, R2[2 * q],     a0);
                a1 = fma2(hv0.y, R2[2 * q + 1], a1);
                a2 = fma2(hv1.x, R2[2 * q + 2], a2);
                a3 = fma2(hv1.y, R2[2 * q + 3], a3);
            }
            const ulonglong2* x4 = (const ulonglong2*)sm_x[b];
            u64 c0 = 0ull, c1 = 0ull;
            #pragma unroll
            for (int q = 0; q < 4; q += 2) {
                ulonglong2 xv0 = x4[q];
                ulonglong2 xv1 = x4[q + 1];
                c0 = fma2(xv0.x, K2[2 * q],     c0);
                c1 = fma2(xv0.y, K2[2 * q + 1], c1);
                c0 = fma2(xv1.x, K2[2 * q + 2], c0);
                c1 = fma2(xv1.y, K2[2 * q + 3], c1);
            }
            float r0, r1;
            unpack2(add2(add2(a0, a1), add2(a2, a3)), r0, r1);
            vr[b] = br + (r0 + r1);
            float x0, x1;
            unpack2(add2(c0, c1), x0, x1);
            vx[b] = bi + (x0 + x1);
        }
        if (tid < NB) dsum += sm_x[tid][15];   // delta accumulation (free)

        #pragma unroll
        for (int b = 0; b < NB; b++) {
            if (g < 128) {
                sm_s[b][g] = vx[b] + vr[b];        // z-pre / r-pre combined
            } else {
                sm_s[b][g]      = vx[b];           // xh
                sm_s[b][g + 64] = vr[b];           // rh
            }
        }
        __syncthreads();

        // ---------- Phase B: gates + prefetch next x ----------
        if (s + 1 < SS && tid >= NB * HH && tid < NB * HH + NB * 4) {
            int t = tid - NB * HH;
            int b = t >> 2, q = t & 3;
            ((float4*)sm_x[b])[q] =
                *(const float4*)&inputs[((size_t)(bbase + b) * SS + (s + 1)) * FIN +
                                        (size_t)q * 4];
        }
        if (tid < NB * HH) {
            int b = tid >> 6, j = tid & 63;
            float z  = sigmoidf_(sm_s[b][j]);
            float r  = sigmoidf_(sm_s[b][64 + j]);
            float hh = tanhf_(sm_s[b][128 + j] + r * sm_s[b][192 + j]);
            float ho = sm_h[b][j];
            sm_h[b][j] = z * (ho - hh) + hh;
        }
        __syncthreads();
    }

    // ---------- Epilogue: delta effect + MLP head + BN ----------
    if (tid < NB) sm_d[tid] = Tp[0] * dsum * (1.0f / (float)SS);
    __syncthreads();

    if (tid < NB * HH) {
        int b = tid >> 6, jj = tid & 63;
        float db  = sm_d[b];
        float acc = b1[jj];
        #pragma unroll 8
        for (int k = 0; k < HH; k++)
            acc += (sm_h[b][k] + db) * w1[k * HH + jj];
        float hr = fmaxf(acc, 0.0f);
        float hb = (hr - bn_mean[jj]) * rsqrtf(bn_var[jj] + 1e-3f) * bn_gamma[jj] + bn_beta[jj];
        sm_e[b][jj] = hb * w2[jj];
    }
    __syncthreads();

    if (tid < NB) {
        float acc = b2[0];
        #pragma unroll 8
        for (int jj = 0; jj < HH; jj++) acc += sm_e[tid][jj];
        out[bbase + tid] = acc;
    }
}

extern "C" void kernel_launch(void* const* d_in, const int* in_sizes, int n_in,
                              void* d_out, int out_size) {
    const float* inputs   = (const float*)d_in[0];
    const float* gk       = (const float*)d_in[1];
    const float* grk      = (const float*)d_in[2];
    const float* gbias    = (const float*)d_in[3];
    const float* w1       = (const float*)d_in[4];
    const float* b1       = (const float*)d_in[5];
    const float* bn_gamma = (const float*)d_in[6];
    const float* bn_beta  = (const float*)d_in[7];
    const float* bn_mean  = (const float*)d_in[8];
    const float* bn_var   = (const float*)d_in[9];
    const float* w2       = (const float*)d_in[10];
    const float* b2       = (const float*)d_in[11];
    const float* T        = (const float*)d_in[12];
    float* out = (float*)d_out;

    gru_scan_kernel<<<NCTA, NT>>>(inputs, gk, grk, gbias, w1, b1,
                                  bn_gamma, bn_beta, bn_mean, bn_var,
                                  w2, b2, T, out);
}